// round 1
// baseline (speedup 1.0000x reference)
#include <cuda_runtime.h>

// FFF (fast feedforward) sparse tree-walk kernel.
// Inputs (metadata order):
//   d_in[0]: oldx  [8192, 768]  float32
//   d_in[1]: w_in  [4095, 768]  float32
//   d_in[2]: w_out [768, 4095]  float32
// Output: [8192, 768] float32
//
// Only 12 nodes per token (root-to-leaf path of a depth-11 binary heap) have a
// nonzero mask, so instead of the dense 8192x4095 GEMMs we walk the tree:
//   logit = dot(x, w_in[cur]); act = gelu_erf(logit);
//   out  += act * w_out[:, cur]; cur = 2*cur + 1 + (logit > 0)

#define FFF_B       8192
#define FFF_D       768
#define FFF_NODES   4095
#define FFF_DEPTH   11
#define FFF_ROW4    (FFF_D / 4)   // 192 float4 per 768-float row

// Transposed w_out scratch: [FFF_NODES, FFF_D] so per-node output columns are
// contiguous, coalesced float4 rows. 12.58 MB static device array (allowed).
__device__ float g_wout_t[(size_t)FFF_NODES * FFF_D];

// ---------------------------------------------------------------------------
// Tiled transpose: w_out [768, 4095] -> g_wout_t [4095, 768]
// blockDim (32, 8); each block handles a 32x32 tile. Coalesced read + write.
// ---------------------------------------------------------------------------
__global__ void fff_transpose_wout(const float* __restrict__ w_out) {
    __shared__ float tile[32][33];
    const int n0 = blockIdx.x * 32;   // node dim (4095)
    const int o0 = blockIdx.y * 32;   // output dim (768)

    const int n = n0 + threadIdx.x;
    #pragma unroll
    for (int j = 0; j < 4; j++) {
        const int o = o0 + threadIdx.y + j * 8;     // o < 768 always (24*32=768)
        if (n < FFF_NODES) {
            tile[threadIdx.y + j * 8][threadIdx.x] = w_out[(size_t)o * FFF_NODES + n];
        }
    }
    __syncthreads();

    const int oo = o0 + threadIdx.x;                // always < 768
    #pragma unroll
    for (int j = 0; j < 4; j++) {
        const int nn = n0 + threadIdx.y + j * 8;
        if (nn < FFF_NODES) {
            g_wout_t[(size_t)nn * FFF_D + oo] = tile[threadIdx.x][threadIdx.y + j * 8];
        }
    }
}

// ---------------------------------------------------------------------------
// Main kernel: one warp per token. x row and output accumulator live in
// registers (6 float4 per lane each). Per level: coalesced float4 load of the
// w_in row, lane-partial dot, butterfly reduce, exact-erf gelu, coalesced
// float4 accumulate of the transposed w_out row, branchless child select.
// ---------------------------------------------------------------------------
__global__ void fff_walk_kernel(const float* __restrict__ x,
                                const float* __restrict__ w_in,
                                float* __restrict__ out) {
    const int warp = (int)((blockIdx.x * blockDim.x + threadIdx.x) >> 5);
    const int lane = threadIdx.x & 31;
    if (warp >= FFF_B) return;

    const float4* __restrict__ x4  = reinterpret_cast<const float4*>(x) + (size_t)warp * FFF_ROW4;
    const float4* __restrict__ wi4 = reinterpret_cast<const float4*>(w_in);
    const float4* __restrict__ wo4 = reinterpret_cast<const float4*>(g_wout_t);

    // Token's x row: 6 float4 per lane, lane-interleaved (coalesced).
    float4 xv[6];
    #pragma unroll
    for (int i = 0; i < 6; i++) xv[i] = x4[i * 32 + lane];

    float4 acc[6];
    #pragma unroll
    for (int i = 0; i < 6; i++) acc[i] = make_float4(0.f, 0.f, 0.f, 0.f);

    int cur = 0;
    #pragma unroll
    for (int d = 0; d <= FFF_DEPTH; d++) {
        // ---- logit = dot(x, w_in[cur]) ----
        const float4* __restrict__ wr = wi4 + (size_t)cur * FFF_ROW4;
        float p0 = 0.f, p1 = 0.f, p2 = 0.f, p3 = 0.f;
        #pragma unroll
        for (int i = 0; i < 6; i += 2) {
            const float4 a = wr[i * 32 + lane];
            const float4 b = wr[(i + 1) * 32 + lane];
            p0 = fmaf(a.x, xv[i].x, p0);
            p1 = fmaf(a.y, xv[i].y, p1);
            p2 = fmaf(a.z, xv[i].z, p2);
            p3 = fmaf(a.w, xv[i].w, p3);
            p0 = fmaf(b.x, xv[i + 1].x, p0);
            p1 = fmaf(b.y, xv[i + 1].y, p1);
            p2 = fmaf(b.z, xv[i + 1].z, p2);
            p3 = fmaf(b.w, xv[i + 1].w, p3);
        }
        float p = (p0 + p1) + (p2 + p3);
        #pragma unroll
        for (int off = 16; off > 0; off >>= 1)
            p += __shfl_xor_sync(0xffffffffu, p, off);

        // ---- exact-erf gelu (matches jax.nn.gelu approximate=False) ----
        const float act = 0.5f * p * (1.0f + erff(p * 0.70710678118654752440f));

        // ---- out += act * w_out[:, cur] (transposed: contiguous row) ----
        const float4* __restrict__ orow = wo4 + (size_t)cur * FFF_ROW4;
        #pragma unroll
        for (int i = 0; i < 6; i++) {
            const float4 w = orow[i * 32 + lane];
            acc[i].x = fmaf(act, w.x, acc[i].x);
            acc[i].y = fmaf(act, w.y, acc[i].y);
            acc[i].z = fmaf(act, w.z, acc[i].z);
            acc[i].w = fmaf(act, w.w, acc[i].w);
        }

        // ---- branchless child: 2*cur + 1 + (logit > 0) ----
        cur = 2 * cur + 1 + (p > 0.0f ? 1 : 0);
    }

    float4* __restrict__ o4 = reinterpret_cast<float4*>(out) + (size_t)warp * FFF_ROW4;
    #pragma unroll
    for (int i = 0; i < 6; i++) o4[i * 32 + lane] = acc[i];
}

extern "C" void kernel_launch(void* const* d_in, const int* in_sizes, int n_in,
                              void* d_out, int out_size) {
    const float* x     = (const float*)d_in[0];
    const float* w_in  = (const float*)d_in[1];
    const float* w_out = (const float*)d_in[2];
    float* out = (float*)d_out;

    // 1) Transpose w_out into node-major scratch (coalesced both sides).
    {
        dim3 block(32, 8);
        dim3 grid((FFF_NODES + 31) / 32, FFF_D / 32);
        fff_transpose_wout<<<grid, block>>>(w_out);
    }

    // 2) Sparse tree walk: 8 warps (tokens) per 256-thread block.
    {
        const int warps_per_block = 8;
        const int threads = warps_per_block * 32;
        const int blocks = FFF_B / warps_per_block;
        fff_walk_kernel<<<blocks, threads>>>(x, w_in, out);
    }
}

// round 2
// speedup vs baseline: 1.2066x; 1.2066x over previous
#include <cuda_runtime.h>

// FFF (fast feedforward) sparse tree-walk kernel, round 2.
// Inputs (metadata order):
//   d_in[0]: oldx  [8192, 768]  float32
//   d_in[1]: w_in  [4095, 768]  float32
//   d_in[2]: w_out [768, 4095]  float32
// Output: [8192, 768] float32
//
// Phase split: (1) serial decision walk computing 12 gelu activations + leaf,
// (2) fully-parallel accumulation of the 12 w_out rows (MLP=12).

#define FFF_B       8192
#define FFF_D       768
#define FFF_NODES   4095
#define FFF_DEPTH   11
#define FFF_LEVELS  (FFF_DEPTH + 1)      // 12 nodes on the path
#define FFF_ROW4    (FFF_D / 4)          // 192 float4 per 768-float row

// Transposed w_out scratch: [FFF_NODES, FFF_D] (node-major, coalesced rows).
__device__ float g_wout_t[(size_t)FFF_NODES * FFF_D];

// ---------------------------------------------------------------------------
// Tiled transpose: w_out [768, 4095] -> g_wout_t [4095, 768]
// ---------------------------------------------------------------------------
__global__ void fff_transpose_wout(const float* __restrict__ w_out) {
    __shared__ float tile[32][33];
    const int n0 = blockIdx.x * 32;   // node dim (4095)
    const int o0 = blockIdx.y * 32;   // output dim (768)

    const int n = n0 + threadIdx.x;
    #pragma unroll
    for (int j = 0; j < 4; j++) {
        const int o = o0 + threadIdx.y + j * 8;     // o < 768 always
        if (n < FFF_NODES) {
            tile[threadIdx.y + j * 8][threadIdx.x] = w_out[(size_t)o * FFF_NODES + n];
        }
    }
    __syncthreads();

    const int oo = o0 + threadIdx.x;                // always < 768
    #pragma unroll
    for (int j = 0; j < 4; j++) {
        const int nn = n0 + threadIdx.y + j * 8;
        if (nn < FFF_NODES) {
            g_wout_t[(size_t)nn * FFF_D + oo] = tile[threadIdx.x][threadIdx.y + j * 8];
        }
    }
}

// ---------------------------------------------------------------------------
// Main kernel: one warp per token.
// Phase 1: serial tree walk -> acts[12] + final virtual node (level 12).
// Phase 2: accumulate 12 independent w_out rows, one float4 chunk at a time.
// ---------------------------------------------------------------------------
__global__ void __launch_bounds__(256, 3)
fff_walk_kernel(const float* __restrict__ x,
                const float* __restrict__ w_in,
                float* __restrict__ out) {
    const int warp = (int)((blockIdx.x * blockDim.x + threadIdx.x) >> 5);
    const int lane = threadIdx.x & 31;
    if (warp >= FFF_B) return;

    const float4* __restrict__ x4  = reinterpret_cast<const float4*>(x) + (size_t)warp * FFF_ROW4;
    const float4* __restrict__ wi4 = reinterpret_cast<const float4*>(w_in);
    const float4* __restrict__ wo4 = reinterpret_cast<const float4*>(g_wout_t);

    // Token's x row: 6 float4 per lane, lane-interleaved (coalesced).
    float4 xv[6];
    #pragma unroll
    for (int i = 0; i < 6; i++) xv[i] = x4[i * 32 + lane];

    // ---------------- Phase 1: serial decision walk ----------------
    float acts[FFF_LEVELS];
    int cur = 0;
    #pragma unroll
    for (int d = 0; d < FFF_LEVELS; d++) {
        const float4* __restrict__ wr = wi4 + (size_t)cur * FFF_ROW4;
        float p0 = 0.f, p1 = 0.f, p2 = 0.f, p3 = 0.f;
        #pragma unroll
        for (int i = 0; i < 6; i += 2) {
            const float4 a = wr[i * 32 + lane];
            const float4 b = wr[(i + 1) * 32 + lane];
            p0 = fmaf(a.x, xv[i].x, p0);
            p1 = fmaf(a.y, xv[i].y, p1);
            p2 = fmaf(a.z, xv[i].z, p2);
            p3 = fmaf(a.w, xv[i].w, p3);
            p0 = fmaf(b.x, xv[i + 1].x, p0);
            p1 = fmaf(b.y, xv[i + 1].y, p1);
            p2 = fmaf(b.z, xv[i + 1].z, p2);
            p3 = fmaf(b.w, xv[i + 1].w, p3);
        }
        float p = (p0 + p1) + (p2 + p3);
        #pragma unroll
        for (int off = 16; off > 0; off >>= 1)
            p += __shfl_xor_sync(0xffffffffu, p, off);

        // exact-erf gelu (matches jax.nn.gelu approximate=False)
        acts[d] = 0.5f * p * (1.0f + erff(p * 0.70710678118654752440f));

        cur = 2 * cur + 1 + (p > 0.0f ? 1 : 0);
    }
    // cur is now the level-12 "virtual" node; path node at level d is
    // ((cur+1) >> (12-d)) - 1  (ancestor chain of the final leaf).
    const unsigned vfinal = (unsigned)(cur + 1);

    unsigned rowoff[FFF_LEVELS];   // float4 offsets of the 12 w_out rows
    #pragma unroll
    for (int d = 0; d < FFF_LEVELS; d++) {
        const unsigned node = (vfinal >> (FFF_LEVELS - d)) - 1u;
        rowoff[d] = node * (unsigned)FFF_ROW4;
    }

    // ---------------- Phase 2: independent accumulation ----------------
    float4* __restrict__ o4 = reinterpret_cast<float4*>(out) + (size_t)warp * FFF_ROW4;
    #pragma unroll
    for (int i = 0; i < 6; i++) {
        const unsigned chunk = (unsigned)(i * 32 + lane);
        float a0 = 0.f, a1 = 0.f, a2 = 0.f, a3 = 0.f;
        #pragma unroll
        for (int d = 0; d < FFF_LEVELS; d++) {
            const float4 w = wo4[rowoff[d] + chunk];   // 12 independent loads
            a0 = fmaf(acts[d], w.x, a0);
            a1 = fmaf(acts[d], w.y, a1);
            a2 = fmaf(acts[d], w.z, a2);
            a3 = fmaf(acts[d], w.w, a3);
        }
        o4[chunk] = make_float4(a0, a1, a2, a3);
    }
}

extern "C" void kernel_launch(void* const* d_in, const int* in_sizes, int n_in,
                              void* d_out, int out_size) {
    const float* x     = (const float*)d_in[0];
    const float* w_in  = (const float*)d_in[1];
    const float* w_out = (const float*)d_in[2];
    float* out = (float*)d_out;

    // 1) Transpose w_out into node-major scratch (coalesced both sides).
    {
        dim3 block(32, 8);
        dim3 grid((FFF_NODES + 31) / 32, FFF_D / 32);
        fff_transpose_wout<<<grid, block>>>(w_out);
    }

    // 2) Sparse tree walk: 8 warps (tokens) per 256-thread block.
    {
        const int warps_per_block = 8;
        const int threads = warps_per_block * 32;
        const int blocks = FFF_B / warps_per_block;
        fff_walk_kernel<<<blocks, threads>>>(x, w_in, out);
    }
}